// round 10
// baseline (speedup 1.0000x reference)
#include <cuda_runtime.h>
#include <cuda_bf16.h>
#include <mma.h>
#include <cstdint>

using namespace nvcuda;

#define T_    128
#define B_    256
#define D_    1024
#define H_    1024
#define V_    32000
#define TAGS_ 1024
#define GQ    32      // 4 gates * 8 qubits

// ---------------- scratch (static device globals; no cudaMalloc allowed) ----
__device__ float          g_embproj[V_ * GQ];              // emb @ Wg_x
__device__ __nv_bfloat16  g_lstm[(size_t)T_ * B_ * H_];    // lstm_out bf16
__device__ __nv_bfloat16  g_wtag[H_ * TAGS_];              // W_tag bf16
__device__ __nv_bfloat16  g_logits[(size_t)T_ * B_ * TAGS_]; // logits bf16

// ---------------- helpers ----------------------------------------------------
__device__ __forceinline__ void cp16(void* smem, const void* gmem) {
    unsigned sa = (unsigned)__cvta_generic_to_shared(smem);
    asm volatile("cp.async.cg.shared.global [%0], [%1], 16;\n" :: "r"(sa), "l"(gmem));
}
__device__ __forceinline__ float fast_sigmoid(float x) {
    return 0.5f + 0.5f * __tanhf(0.5f * x);
}
__device__ __forceinline__ float bflo(uint32_t v) { return __uint_as_float(v << 16); }
__device__ __forceinline__ float bfhi(uint32_t v) { return __uint_as_float(v & 0xffff0000u); }

// ---------------- K0: W_tag -> bf16 -----------------------------------------
__global__ void wtag_convert(const float* __restrict__ w) {
    int i = blockIdx.x * 256 + threadIdx.x;
    g_wtag[i] = __float2bfloat16(w[i]);
}

// ---------------- K1: embproj = emb @ Wg[:, :D, :]  (32000 x 32) ------------
__global__ __launch_bounds__(256) void embproj_kernel(const float* __restrict__ emb,
                                                      const float* __restrict__ Wg) {
    __shared__ float As[128][33];
    __shared__ __align__(16) float Bs[32][36];
    int tid = threadIdx.x;
    int v0  = blockIdx.x * 128;
    int tr  = tid >> 3, tc = tid & 7;
    float acc[4][4] = {};

    for (int k0 = 0; k0 < D_; k0 += 32) {
        #pragma unroll
        for (int i = 0; i < 4; i++) {
            int f4  = tid + i * 256;
            int row = f4 >> 3, c4 = (f4 & 7) * 4;
            float4 a = *(const float4*)&emb[(size_t)(v0 + row) * D_ + k0 + c4];
            As[row][c4] = a.x; As[row][c4 + 1] = a.y;
            As[row][c4 + 2] = a.z; As[row][c4 + 3] = a.w;
        }
        #pragma unroll
        for (int i = 0; i < 4; i++) {
            int idx = tid + i * 256;
            int k = idx >> 5, gq = idx & 31;
            Bs[k][gq] = Wg[(gq >> 3) * (2048 * 8) + (k0 + k) * 8 + (gq & 7)];
        }
        __syncthreads();
        #pragma unroll
        for (int k = 0; k < 32; k++) {
            float4 b4 = *(const float4*)&Bs[k][tc * 4];
            #pragma unroll
            for (int i = 0; i < 4; i++) {
                float a = As[tr * 4 + i][k];
                acc[i][0] += a * b4.x; acc[i][1] += a * b4.y;
                acc[i][2] += a * b4.z; acc[i][3] += a * b4.w;
            }
        }
        __syncthreads();
    }
    #pragma unroll
    for (int i = 0; i < 4; i++) {
        float4 o = make_float4(acc[i][0], acc[i][1], acc[i][2], acc[i][3]);
        *(float4*)&g_embproj[(v0 + tr * 4 + i) * GQ + tc * 4] = o;
    }
}

// ---------------- K2: LSTM, k-split matvec (lane = gq, warp = k-slice) -------
// 512 thr/CTA, 2 hidden units/thread, 2 batch/CTA, 128 CTAs (1 wave).
#define LSTM_SMEM ((16384 + 2 * 1024 + 2 * 4096 + 64 + 2 * 16 * 33) * 4)

__device__ __forceinline__ void gate_update(const float4* qc, const float* wp,
                                            const float* bpv, float& c, float& h) {
    float pj[4];
    #pragma unroll
    for (int g = 0; g < 4; g++) {
        float4 a = qc[2 * g], b = qc[2 * g + 1];
        float s = bpv[g];
        s = fmaf(a.x, wp[g * 8 + 0], s); s = fmaf(a.y, wp[g * 8 + 1], s);
        s = fmaf(a.z, wp[g * 8 + 2], s); s = fmaf(a.w, wp[g * 8 + 3], s);
        s = fmaf(b.x, wp[g * 8 + 4], s); s = fmaf(b.y, wp[g * 8 + 5], s);
        s = fmaf(b.z, wp[g * 8 + 6], s); s = fmaf(b.w, wp[g * 8 + 7], s);
        pj[g] = s;
    }
    float fg = fast_sigmoid(pj[0]);
    float ig = fast_sigmoid(pj[1]);
    float gg = __tanhf(pj[2]);
    float og = fast_sigmoid(pj[3]);
    c = fg * c + ig * gg;
    h = og * __tanhf(c);
}

__global__ __launch_bounds__(512, 1) void lstm_kernel(
    const int*   __restrict__ sentence,
    const float* __restrict__ Wg,
    const float* __restrict__ bg,
    const float* __restrict__ theta,
    const float* __restrict__ Wp,
    const float* __restrict__ bp) {
    extern __shared__ float sm[];
    uint32_t* Wkp = (uint32_t*)sm;         // [512 kp][32 gq] bf16x2
    float* h0s  = sm + 16384;              // 1024
    float* h1s  = h0s + 1024;              // 1024
    float* xq0  = h1s + 1024;              // 4096
    float* xq1  = xq0 + 4096;              // 4096
    float* qc0  = xq1 + 4096;              // 32 (16B aligned)
    float* qc1  = qc0 + 32;                // 32
    float* red0 = qc1 + 32;                // 16 x 33
    float* red1 = red0 + 16 * 33;          // 16 x 33

    const int tid  = threadIdx.x;
    const int warp = tid >> 5, lane = tid & 31;
    const int b0   = blockIdx.x * 2;

    // Wkp[kp][gq] = bf16x2(Wg[g][D+2kp][q], Wg[g][D+2kp+1][q]),  gq = g*8+q
    #pragma unroll 4
    for (int it = 0; it < 32; it++) {
        int p  = tid + it * 512;            // 16384 total
        int kp = p >> 5, gq = p & 31;
        int g  = gq >> 3, q = gq & 7;
        const float* src = Wg + g * (2048 * 8) + (size_t)(1024 + 2 * kp) * 8 + q;
        uint32_t l16 = (uint32_t)__bfloat16_as_ushort(__float2bfloat16(src[0]));
        uint32_t h16 = (uint32_t)__bfloat16_as_ushort(__float2bfloat16(src[8]));
        Wkp[kp * 32 + gq] = l16 | (h16 << 16);
    }
    // xq[b][t][gq] = embproj[token][gq] + bg[gq] + theta[gq]
    #pragma unroll
    for (int it = 0; it < 16; it++) {
        int p  = tid + it * 512;
        int bb = p >> 12, r = p & 4095;
        int t  = r >> 5, gq = r & 31;
        int token = sentence[t * B_ + b0 + bb];
        (bb ? xq1 : xq0)[t * 32 + gq] =
            g_embproj[token * GQ + gq] + bg[gq] + theta[gq];
    }
    // per-thread Wp slices for j = tid and j = tid + 512
    float wpreg[64], bpv[8];
    #pragma unroll
    for (int k = 0; k < 32; k++) {
        wpreg[k]      = Wp[k * H_ + tid];
        wpreg[32 + k] = Wp[k * H_ + tid + 512];
    }
    #pragma unroll
    for (int g = 0; g < 4; g++) {
        bpv[g]     = bp[g * H_ + tid];
        bpv[4 + g] = bp[g * H_ + tid + 512];
    }

    h0s[tid] = 0.f; h0s[tid + 512] = 0.f;
    h1s[tid] = 0.f; h1s[tid + 512] = 0.f;
    float h0a = 0.f, h0b = 0.f, h1a = 0.f, h1b = 0.f;
    float c0a = 0.f, c0b = 0.f, c1a = 0.f, c1b = 0.f;
    __syncthreads();

    // warp's k-pair slice: kp in [32*warp, 32*warp+32)  (k in [64w, 64w+64))
    const uint32_t* wrow = Wkp + (32 * warp) * 32 + lane;
    const float4*   h0v  = (const float4*)(h0s + 64 * warp);   // 16 float4
    const float4*   h1v  = (const float4*)(h1s + 64 * warp);
    const int rgq = 2 * warp + (lane >> 4);   // gq reduced by this half-warp
    const int ri  = lane & 15;

    for (int t = 0; t < T_; t++) {
        // matvec partials: lane = gq; split into 2 independent chain groups
        float a0x = 0.f, a0y = 0.f, a1x = 0.f, a1y = 0.f;
        #pragma unroll
        for (int i = 0; i < 8; i++) {
            uint32_t w0 = wrow[(2 * i) * 32];
            uint32_t w1 = wrow[(2 * i + 1) * 32];
            uint32_t w2 = wrow[(2 * i + 16) * 32];
            uint32_t w3 = wrow[(2 * i + 17) * 32];
            float4 p0 = h0v[i],     q0 = h1v[i];
            float4 p1 = h0v[i + 8], q1 = h1v[i + 8];
            a0x = fmaf(bflo(w0), p0.x, a0x); a0x = fmaf(bfhi(w0), p0.y, a0x);
            a0x = fmaf(bflo(w1), p0.z, a0x); a0x = fmaf(bfhi(w1), p0.w, a0x);
            a1x = fmaf(bflo(w0), q0.x, a1x); a1x = fmaf(bfhi(w0), q0.y, a1x);
            a1x = fmaf(bflo(w1), q0.z, a1x); a1x = fmaf(bfhi(w1), q0.w, a1x);
            a0y = fmaf(bflo(w2), p1.x, a0y); a0y = fmaf(bfhi(w2), p1.y, a0y);
            a0y = fmaf(bflo(w3), p1.z, a0y); a0y = fmaf(bfhi(w3), p1.w, a0y);
            a1y = fmaf(bflo(w2), q1.x, a1y); a1y = fmaf(bfhi(w2), q1.y, a1y);
            a1y = fmaf(bflo(w3), q1.z, a1y); a1y = fmaf(bfhi(w3), q1.w, a1y);
        }
        red0[warp * 33 + lane] = a0x + a0y;
        red1[warp * 33 + lane] = a1x + a1y;
        __syncthreads();
        {
            float v0 = red0[ri * 33 + rgq];
            float v1 = red1[ri * 33 + rgq];
            #pragma unroll
            for (int off = 8; off > 0; off >>= 1) {
                v0 += __shfl_xor_sync(~0u, v0, off);
                v1 += __shfl_xor_sync(~0u, v1, off);
            }
            if (ri == 0) {
                qc0[rgq] = __cosf(v0 + xq0[t * 32 + rgq]);
                qc1[rgq] = __cosf(v1 + xq1[t * 32 + rgq]);
            }
        }
        __syncthreads();

        const float4* q0 = (const float4*)qc0;
        const float4* q1 = (const float4*)qc1;
        gate_update(q0, wpreg,      bpv,     c0a, h0a);
        gate_update(q0, wpreg + 32, bpv + 4, c0b, h0b);
        gate_update(q1, wpreg,      bpv,     c1a, h1a);
        gate_update(q1, wpreg + 32, bpv + 4, c1b, h1b);

        size_t base = ((size_t)t * B_ + b0) * H_;
        g_lstm[base + tid]            = __float2bfloat16(h0a);
        g_lstm[base + tid + 512]      = __float2bfloat16(h0b);
        g_lstm[base + H_ + tid]       = __float2bfloat16(h1a);
        g_lstm[base + H_ + tid + 512] = __float2bfloat16(h1b);
        h0s[tid] = h0a; h0s[tid + 512] = h0b;
        h1s[tid] = h1a; h1s[tid + 512] = h1b;
        __syncthreads();
    }
}

// ---------------- K3: tag GEMM (bf16 WMMA, 128x128 tiles, 2 CTA/SM) ----------
// grid (8, 2, 128) = 2048 CTAs. 8 warps x (32x64). 3-stage cp.async, KT = 64.
// Writes bf16 logits; softmax (and b_tag cancellation) handled in K4.
#define A_STG2 (128 * 72)    // halves per A stage (ld = 72)
#define B_STG2 (64 * 136)    // halves per B stage (ld = 136)
#define TG_SMEM (3 * (A_STG2 + B_STG2) * 2)   // 107,520 B -> 2 CTA/SM

__global__ __launch_bounds__(256, 2) void tag_gemm() {
    extern __shared__ char smraw[];
    __nv_bfloat16* Asm = (__nv_bfloat16*)smraw;        // 3 stages 128x72
    __nv_bfloat16* Bsm = Asm + 3 * A_STG2;             // 3 stages 64x136
    float* Osm = (float*)smraw;                        // 128 x 136 fp32 (alias)

    const int tid = threadIdx.x;
    const int c0  = blockIdx.x * 128;
    const int b0  = blockIdx.y * 128;
    const int t   = blockIdx.z;
    const int w   = tid >> 5;
    const int wy  = w >> 1;        // 0..3 -> 32-row block
    const int wx  = w & 1;         // 0..1 -> 64-col block

    wmma::fragment<wmma::accumulator, 16, 16, 16, float> acc[2][4];
    #pragma unroll
    for (int i = 0; i < 2; i++)
        #pragma unroll
        for (int j = 0; j < 4; j++) wmma::fill_fragment(acc[i][j], 0.f);

    auto issue_tile = [&](int kt) {
        int s  = kt % 3;
        int k0 = kt * 64;
        __nv_bfloat16* As = Asm + s * A_STG2;
        __nv_bfloat16* Bs = Bsm + s * B_STG2;
        #pragma unroll
        for (int i = 0; i < 4; i++) {             // A: 128x64 = 1024 cp16
            int e = tid + i * 256;
            int row = e >> 3, c8 = (e & 7) * 8;
            cp16(&As[row * 72 + c8],
                 &g_lstm[((size_t)t * B_ + b0 + row) * H_ + k0 + c8]);
        }
        #pragma unroll
        for (int i = 0; i < 4; i++) {             // B: 64x128 = 1024 cp16
            int e = tid + i * 256;
            int row = e >> 4, c8 = (e & 15) * 8;
            cp16(&Bs[row * 136 + c8],
                 &g_wtag[(size_t)(k0 + row) * TAGS_ + c0 + c8]);
        }
        asm volatile("cp.async.commit_group;\n" ::);
    };

    issue_tile(0);
    issue_tile(1);
    for (int kt = 0; kt < 16; kt++) {
        if (kt < 15) asm volatile("cp.async.wait_group 1;\n" ::);
        else         asm volatile("cp.async.wait_group 0;\n" ::);
        __syncthreads();   // stage kt ready everywhere; compute kt-1 done
        int s = kt % 3;
        const __nv_bfloat16* As = Asm + s * A_STG2;
        const __nv_bfloat16* Bs = Bsm + s * B_STG2;
        #pragma unroll
        for (int ks = 0; ks < 64; ks += 16) {
            wmma::fragment<wmma::matrix_a, 16, 16, 16, __nv_bfloat16, wmma::row_major> af[2];
            wmma::fragment<wmma::matrix_b, 16, 16, 16, __nv_bfloat16, wmma::row_major> bf[4];
            #pragma unroll
            for (int i = 0; i < 2; i++)
                wmma::load_matrix_sync(af[i], &As[(wy * 32 + i * 16) * 72 + ks], 72);
            #pragma unroll
            for (int j = 0; j < 4; j++)
                wmma::load_matrix_sync(bf[j], &Bs[ks * 136 + wx * 64 + j * 16], 136);
            #pragma unroll
            for (int i = 0; i < 2; i++)
                #pragma unroll
                for (int j = 0; j < 4; j++)
                    wmma::mma_sync(acc[i][j], af[i], bf[j], acc[i][j]);
        }
        if (kt + 2 < 16) issue_tile(kt + 2);
    }
    __syncthreads();   // all compute done before Osm aliases stage buffers

    #pragma unroll
    for (int i = 0; i < 2; i++)
        #pragma unroll
        for (int j = 0; j < 4; j++)
            wmma::store_matrix_sync(&Osm[(wy * 32 + i * 16) * 136 + wx * 64 + j * 16],
                                    acc[i][j], 136, wmma::mem_row_major);
    __syncthreads();

    // write bf16 logits (coalesced: 64 uint32 per 128-col row)
    #pragma unroll
    for (int i = 0; i < 32; i++) {
        int e   = tid + i * 256;
        int row = e >> 6, cu = e & 63;
        float lo = Osm[row * 136 + cu * 2];
        float hi = Osm[row * 136 + cu * 2 + 1];
        __nv_bfloat162 pk = __float22bfloat162_rn(make_float2(lo, hi));
        *(uint32_t*)&g_logits[((size_t)t * B_ + b0 + row) * TAGS_ + c0 + cu * 2] =
            *(uint32_t*)&pk;
    }
}

// ---------------- K4: log_softmax over batch axis (b_tag cancels) ------------
#define SMX_SMEM (256 * 136 * 4 + 512 * 4)

__global__ __launch_bounds__(512, 1) void softmax_kernel(float* __restrict__ out) {
    extern __shared__ float sm[];
    float* Osm = sm;                    // 256 x 136
    float* red = sm + 256 * 136;
    const int tid = threadIdx.x;
    const int t = blockIdx.y, c0 = blockIdx.x * 128;

    #pragma unroll
    for (int i = 0; i < 8; i++) {       // 4096 uint4 of 8 bf16
        int e = tid + i * 512;
        int row = e >> 4, cg = (e & 15) * 8;
        uint4 v = *(const uint4*)&g_logits[((size_t)t * B_ + row) * TAGS_ + c0 + cg];
        float* d = &Osm[row * 136 + cg];
        uint32_t ws[4] = {v.x, v.y, v.z, v.w};
        #pragma unroll
        for (int q = 0; q < 4; q++) {
            d[2 * q]     = __uint_as_float(ws[q] << 16);
            d[2 * q + 1] = __uint_as_float(ws[q] & 0xffff0000u);
        }
    }
    __syncthreads();

    const int p = tid >> 7, c = tid & 127;       // 4 partials x 64 rows
    float m = -1e30f;
    #pragma unroll 8
    for (int i = 0; i < 64; i++) m = fmaxf(m, Osm[(p * 64 + i) * 136 + c]);
    red[p * 128 + c] = m;
    __syncthreads();
    float M = fmaxf(fmaxf(red[c], red[128 + c]), fmaxf(red[256 + c], red[384 + c]));
    float ssum = 0.f;
    #pragma unroll 8
    for (int i = 0; i < 64; i++) ssum += __expf(Osm[(p * 64 + i) * 136 + c] - M);
    __syncthreads();
    red[p * 128 + c] = ssum;
    __syncthreads();
    float lse = M + logf(red[c] + red[128 + c] + red[256 + c] + red[384 + c]);
    #pragma unroll 8
    for (int i = 0; i < 64; i++) {
        int b = p * 64 + i;
        out[((size_t)t * B_ + b) * TAGS_ + c0 + c] = Osm[b * 136 + c] - lse;
    }
}

// ---------------- launch -----------------------------------------------------
extern "C" void kernel_launch(void* const* d_in, const int* in_sizes, int n_in,
                              void* d_out, int out_size) {
    const int*   sentence = (const int*)  d_in[0];
    const float* emb      = (const float*)d_in[1];
    const float* Wg       = (const float*)d_in[2];
    const float* bg       = (const float*)d_in[3];
    const float* theta    = (const float*)d_in[4];
    const float* Wp       = (const float*)d_in[5];
    const float* bp       = (const float*)d_in[6];
    const float* W_tag    = (const float*)d_in[7];
    // d_in[8] = b_tag: cancels in log_softmax over batch axis -> unused
    float* out = (float*)d_out;

    cudaFuncSetAttribute(lstm_kernel,    cudaFuncAttributeMaxDynamicSharedMemorySize, LSTM_SMEM);
    cudaFuncSetAttribute(tag_gemm,       cudaFuncAttributeMaxDynamicSharedMemorySize, TG_SMEM);
    cudaFuncSetAttribute(softmax_kernel, cudaFuncAttributeMaxDynamicSharedMemorySize, SMX_SMEM);

    wtag_convert<<<(H_ * TAGS_) / 256, 256>>>(W_tag);
    embproj_kernel<<<V_ / 128, 256>>>(emb, Wg);
    lstm_kernel<<<B_ / 2, 512, LSTM_SMEM>>>(sentence, Wg, bg, theta, Wp, bp);
    tag_gemm<<<dim3(TAGS_ / 128, B_ / 128, T_), 256, TG_SMEM>>>();
    softmax_kernel<<<dim3(TAGS_ / 128, T_), 512, SMX_SMEM>>>(out);
}

// round 12
// speedup vs baseline: 1.1774x; 1.1774x over previous
#include <cuda_runtime.h>
#include <cuda_bf16.h>
#include <mma.h>
#include <cstdint>

using namespace nvcuda;

#define T_    128
#define B_    256
#define D_    1024
#define H_    1024
#define V_    32000
#define TAGS_ 1024
#define GQ    32      // 4 gates * 8 qubits

// ---------------- scratch (static device globals; no cudaMalloc allowed) ----
__device__ float          g_embproj[V_ * GQ];           // emb @ Wg_x
__device__ __nv_bfloat16  g_lstm[(size_t)T_ * B_ * H_]; // lstm_out bf16
__device__ __nv_bfloat16  g_wtag[H_ * TAGS_];           // W_tag bf16

// ---------------- helpers ----------------------------------------------------
__device__ __forceinline__ void cp16(void* smem, const void* gmem) {
    unsigned sa = (unsigned)__cvta_generic_to_shared(smem);
    asm volatile("cp.async.cg.shared.global [%0], [%1], 16;\n" :: "r"(sa), "l"(gmem));
}
__device__ __forceinline__ float fast_sigmoid(float x) {
    return 0.5f + 0.5f * __tanhf(0.5f * x);
}
__device__ __forceinline__ float bflo(uint32_t v) { return __uint_as_float(v << 16); }
__device__ __forceinline__ float bfhi(uint32_t v) { return __uint_as_float(v & 0xffff0000u); }

// ---------------- K0: W_tag -> bf16 -----------------------------------------
__global__ void wtag_convert(const float* __restrict__ w) {
    int i = blockIdx.x * 256 + threadIdx.x;
    g_wtag[i] = __float2bfloat16(w[i]);
}

// ---------------- K1: embproj = emb @ Wg_x  via bf16 WMMA --------------------
// grid = 125 CTAs x 256 thr; CTA tile 256 rows x 32 cols, K = 1024.
// B (Wg_x) bf16 in smem once; A converted fp32->bf16 per k-tile with register
// double-buffering. Output tile aliases the B REGION (large enough: 80KB).
#define EP_BS   (1024 * 40)            // B smem halves (ld = 40) = 80 KB
#define EP_AS   (256 * 72)             // A smem halves (ld = 72) = 36 KB
#define EP_SMEM (EP_BS * 2 + EP_AS * 2)

__global__ __launch_bounds__(256, 1) void embproj_kernel(const float* __restrict__ emb,
                                                         const float* __restrict__ Wg) {
    extern __shared__ char smraw[];
    __nv_bfloat16* Bs = (__nv_bfloat16*)smraw;       // [1024][40]
    __nv_bfloat16* As = Bs + EP_BS;                  // [256][72]
    float* Osm = (float*)smraw;                      // alias B region: [256][40] fp32 (40KB <= 80KB)

    const int tid = threadIdx.x;
    const int v0  = blockIdx.x * 256;
    const int w   = tid >> 5;                        // warp -> 32-row block

    // B: Wg[g][k][q] -> Bs[k][gq] bf16 (1024x32, 128 elems/thread)
    #pragma unroll 4
    for (int i = 0; i < 128; i++) {
        int idx = tid + i * 256;                     // 32768
        int k = idx >> 5, gq = idx & 31;
        Bs[k * 40 + gq] = __float2bfloat16(
            Wg[(gq >> 3) * (2048 * 8) + k * 8 + (gq & 7)]);
    }

    // register prefetch of A k-tile 0 (256x64 fp32, 16 float4/thread)
    float4 buf[16];
    #pragma unroll
    for (int i = 0; i < 16; i++) {
        int e = tid + i * 256;                       // 4096 float4
        int row = e >> 4, c4 = (e & 15) * 4;
        buf[i] = *(const float4*)&emb[(size_t)(v0 + row) * D_ + c4];
    }
    __syncthreads();                                 // Bs ready

    wmma::fragment<wmma::accumulator, 16, 16, 16, float> acc[2][2];
    #pragma unroll
    for (int i = 0; i < 2; i++)
        #pragma unroll
        for (int j = 0; j < 2; j++) wmma::fill_fragment(acc[i][j], 0.f);

    for (int kt = 0; kt < 16; kt++) {
        // buf -> As (cvt bf16), pairs of float4 -> one 16B store
        #pragma unroll
        for (int i = 0; i < 8; i++) {
            int e = tid + i * 256;                   // 2048 8-elem groups
            int row = e >> 3, c8 = (e & 7) * 8;
            float4 a = buf[2 * i], b = buf[2 * i + 1];
            __nv_bfloat162 p0 = __float22bfloat162_rn(make_float2(a.x, a.y));
            __nv_bfloat162 p1 = __float22bfloat162_rn(make_float2(a.z, a.w));
            __nv_bfloat162 p2 = __float22bfloat162_rn(make_float2(b.x, b.y));
            __nv_bfloat162 p3 = __float22bfloat162_rn(make_float2(b.z, b.w));
            uint4 pk = make_uint4(*(uint32_t*)&p0, *(uint32_t*)&p1,
                                  *(uint32_t*)&p2, *(uint32_t*)&p3);
            *(uint4*)&As[row * 72 + c8] = pk;
        }
        __syncthreads();
        if (kt < 15) {
            int k0n = (kt + 1) * 64;
            #pragma unroll
            for (int i = 0; i < 16; i++) {
                int e = tid + i * 256;
                int row = e >> 4, c4 = (e & 15) * 4;
                buf[i] = *(const float4*)&emb[(size_t)(v0 + row) * D_ + k0n + c4];
            }
        }
        #pragma unroll
        for (int ks = 0; ks < 64; ks += 16) {
            wmma::fragment<wmma::matrix_a, 16, 16, 16, __nv_bfloat16, wmma::row_major> af[2];
            wmma::fragment<wmma::matrix_b, 16, 16, 16, __nv_bfloat16, wmma::row_major> bf[2];
            #pragma unroll
            for (int i = 0; i < 2; i++)
                wmma::load_matrix_sync(af[i], &As[(w * 32 + i * 16) * 72 + ks], 72);
            #pragma unroll
            for (int j = 0; j < 2; j++)
                wmma::load_matrix_sync(bf[j], &Bs[(kt * 64 + ks) * 40 + j * 16], 40);
            #pragma unroll
            for (int i = 0; i < 2; i++)
                #pragma unroll
                for (int j = 0; j < 2; j++)
                    wmma::mma_sync(acc[i][j], af[i], bf[j], acc[i][j]);
        }
        __syncthreads();                             // done reading As
    }
    // NOTE: last loop iteration ended with __syncthreads(), so every warp has
    // finished its MMAs reading Bs; safe to alias Osm onto the B region now.

    #pragma unroll
    for (int i = 0; i < 2; i++)
        #pragma unroll
        for (int j = 0; j < 2; j++)
            wmma::store_matrix_sync(&Osm[(w * 32 + i * 16) * 40 + j * 16],
                                    acc[i][j], 40, wmma::mem_row_major);
    __syncthreads();
    #pragma unroll
    for (int i = 0; i < 8; i++) {
        int e = tid + i * 256;                       // 2048 float4
        int row = e >> 3, c4 = (e & 7) * 4;
        float4 o = make_float4(Osm[row * 40 + c4],     Osm[row * 40 + c4 + 1],
                               Osm[row * 40 + c4 + 2], Osm[row * 40 + c4 + 3]);
        *(float4*)&g_embproj[(size_t)(v0 + row) * GQ + c4] = o;
    }
}

// ---------------- K2: LSTM, full-dot-per-warp matvec (2 barriers/step) -------
// 512 thr/CTA, 2 hidden units/thread, 2 batch/CTA, 128 CTAs (1 wave).
// Warp w owns gq pair (2w, 2w+1); lane owns k-slice; in-warp shuffle reduce.
#define LSTM_SMEM ((16384 + 2 * 1024 + 2 * 4096 + 64) * 4)

__device__ __forceinline__ void gate_update(const float4* qc, const float* wp,
                                            const float* bpv, float& c, float& h) {
    float pj[4];
    #pragma unroll
    for (int g = 0; g < 4; g++) {
        float4 a = qc[2 * g], b = qc[2 * g + 1];
        float s = bpv[g];
        s = fmaf(a.x, wp[g * 8 + 0], s); s = fmaf(a.y, wp[g * 8 + 1], s);
        s = fmaf(a.z, wp[g * 8 + 2], s); s = fmaf(a.w, wp[g * 8 + 3], s);
        s = fmaf(b.x, wp[g * 8 + 4], s); s = fmaf(b.y, wp[g * 8 + 5], s);
        s = fmaf(b.z, wp[g * 8 + 6], s); s = fmaf(b.w, wp[g * 8 + 7], s);
        pj[g] = s;
    }
    float fg = fast_sigmoid(pj[0]);
    float ig = fast_sigmoid(pj[1]);
    float gg = __tanhf(pj[2]);
    float og = fast_sigmoid(pj[3]);
    c = fg * c + ig * gg;
    h = og * __tanhf(c);
}

__global__ __launch_bounds__(512, 1) void lstm_kernel(
    const int*   __restrict__ sentence,
    const float* __restrict__ Wg,
    const float* __restrict__ bg,
    const float* __restrict__ theta,
    const float* __restrict__ Wp,
    const float* __restrict__ bp) {
    extern __shared__ float sm[];
    uint32_t* Wkp = (uint32_t*)sm;         // [32 gq][512 kp] bf16x2
    float* h0s = sm + 16384;               // 1024
    float* h1s = h0s + 1024;               // 1024
    float* xq0 = h1s + 1024;               // 4096
    float* xq1 = xq0 + 4096;               // 4096
    float* qc0 = xq1 + 4096;               // 32 (16B aligned)
    float* qc1 = qc0 + 32;                 // 32

    const int tid  = threadIdx.x;
    const int warp = tid >> 5, lane = tid & 31;
    const int b0   = blockIdx.x * 2;

    // Wkp[gq][kp] = bf16x2(Wg[g][D+2kp][q], Wg[g][D+2kp+1][q])
    #pragma unroll 4
    for (int it = 0; it < 32; it++) {
        int p  = tid + it * 512;            // 16384 total
        int gq = p >> 9, kp = p & 511;
        int g  = gq >> 3, q = gq & 7;
        const float* src = Wg + g * (2048 * 8) + (size_t)(1024 + 2 * kp) * 8 + q;
        uint32_t l16 = (uint32_t)__bfloat16_as_ushort(__float2bfloat16(src[0]));
        uint32_t h16 = (uint32_t)__bfloat16_as_ushort(__float2bfloat16(src[8]));
        Wkp[gq * 512 + kp] = l16 | (h16 << 16);
    }
    // xq[b][t][gq] = embproj[token][gq] + bg[gq] + theta[gq]
    #pragma unroll
    for (int it = 0; it < 16; it++) {
        int p  = tid + it * 512;
        int bb = p >> 12, r = p & 4095;
        int t  = r >> 5, gq = r & 31;
        int token = sentence[t * B_ + b0 + bb];
        (bb ? xq1 : xq0)[t * 32 + gq] =
            g_embproj[token * GQ + gq] + bg[gq] + theta[gq];
    }
    // per-thread Wp slices for j = tid and j = tid + 512
    float wpreg[64], bpv[8];
    #pragma unroll
    for (int k = 0; k < 32; k++) {
        wpreg[k]      = Wp[k * H_ + tid];
        wpreg[32 + k] = Wp[k * H_ + tid + 512];
    }
    #pragma unroll
    for (int g = 0; g < 4; g++) {
        bpv[g]     = bp[g * H_ + tid];
        bpv[4 + g] = bp[g * H_ + tid + 512];
    }

    h0s[tid] = 0.f; h0s[tid + 512] = 0.f;
    h1s[tid] = 0.f; h1s[tid + 512] = 0.f;
    float h0a = 0.f, h0b = 0.f, h1a = 0.f, h1b = 0.f;
    float c0a = 0.f, c0b = 0.f, c1a = 0.f, c1b = 0.f;
    __syncthreads();

    const int gq0 = 2 * warp, gq1 = 2 * warp + 1;
    const uint32_t* w0row = Wkp + gq0 * 512;
    const uint32_t* w1row = Wkp + gq1 * 512;
    const float2* h0p = (const float2*)h0s;
    const float2* h1p = (const float2*)h1s;

    for (int t = 0; t < T_; t++) {
        // full dot products: a[batch][gq-of-pair]
        float a00 = 0.f, a01 = 0.f, a10 = 0.f, a11 = 0.f;
        #pragma unroll
        for (int i = 0; i < 16; i++) {
            int kp = lane + 32 * i;
            uint32_t wv0 = w0row[kp];
            uint32_t wv1 = w1row[kp];
            float2 hA = h0p[kp];
            float2 hB = h1p[kp];
            a00 = fmaf(bflo(wv0), hA.x, a00); a00 = fmaf(bfhi(wv0), hA.y, a00);
            a01 = fmaf(bflo(wv1), hA.x, a01); a01 = fmaf(bfhi(wv1), hA.y, a01);
            a10 = fmaf(bflo(wv0), hB.x, a10); a10 = fmaf(bfhi(wv0), hB.y, a10);
            a11 = fmaf(bflo(wv1), hB.x, a11); a11 = fmaf(bfhi(wv1), hB.y, a11);
        }
        #pragma unroll
        for (int off = 16; off > 0; off >>= 1) {
            a00 += __shfl_xor_sync(~0u, a00, off);
            a01 += __shfl_xor_sync(~0u, a01, off);
            a10 += __shfl_xor_sync(~0u, a10, off);
            a11 += __shfl_xor_sync(~0u, a11, off);
        }
        if (lane == 0) {
            qc0[gq0] = __cosf(a00 + xq0[t * 32 + gq0]);
            qc0[gq1] = __cosf(a01 + xq0[t * 32 + gq1]);
            qc1[gq0] = __cosf(a10 + xq1[t * 32 + gq0]);
            qc1[gq1] = __cosf(a11 + xq1[t * 32 + gq1]);
        }
        __syncthreads();

        const float4* q0 = (const float4*)qc0;
        const float4* q1 = (const float4*)qc1;
        gate_update(q0, wpreg,      bpv,     c0a, h0a);
        gate_update(q0, wpreg + 32, bpv + 4, c0b, h0b);
        gate_update(q1, wpreg,      bpv,     c1a, h1a);
        gate_update(q1, wpreg + 32, bpv + 4, c1b, h1b);

        size_t base = ((size_t)t * B_ + b0) * H_;
        g_lstm[base + tid]            = __float2bfloat16(h0a);
        g_lstm[base + tid + 512]      = __float2bfloat16(h0b);
        g_lstm[base + H_ + tid]       = __float2bfloat16(h1a);
        g_lstm[base + H_ + tid + 512] = __float2bfloat16(h1b);
        h0s[tid] = h0a; h0s[tid + 512] = h0b;
        h1s[tid] = h1a; h1s[tid + 512] = h1b;
        __syncthreads();
    }
}

// ---------------- K3: fused tag GEMM (R9: bf16 WMMA 64x64, 3-stage) ----------
#define A_STG (256 * 72)     // halves per A stage (ld = 72)
#define B_STG (64 * 136)     // halves per B stage (ld = 136)
#define TAG_SMEM (3 * (A_STG + B_STG) * 2)

__global__ __launch_bounds__(256, 1) void tag_kernel(float* __restrict__ out) {
    extern __shared__ char smraw[];
    __nv_bfloat16* Asm = (__nv_bfloat16*)smraw;        // 3 stages 256x72
    __nv_bfloat16* Bsm = Asm + 3 * A_STG;              // 3 stages 64x136
    float* Osm = (float*)smraw;                        // 256 x 136 fp32 (alias)
    float* red = Osm + 256 * 136;

    const int tid = threadIdx.x;
    const int t   = blockIdx.y;
    const int c0  = blockIdx.x * 128;
    const int w   = tid >> 5;
    const int wy  = w >> 1;
    const int wx  = w & 1;

    wmma::fragment<wmma::accumulator, 16, 16, 16, float> acc[4][4];
    #pragma unroll
    for (int i = 0; i < 4; i++)
        #pragma unroll
        for (int j = 0; j < 4; j++) wmma::fill_fragment(acc[i][j], 0.f);

    auto issue_tile = [&](int kt) {
        int s  = kt % 3;
        int k0 = kt * 64;
        __nv_bfloat16* As = Asm + s * A_STG;
        __nv_bfloat16* Bs = Bsm + s * B_STG;
        #pragma unroll
        for (int i = 0; i < 8; i++) {
            int e = tid + i * 256;
            int row = e >> 3, c8 = (e & 7) * 8;
            cp16(&As[row * 72 + c8],
                 &g_lstm[((size_t)t * B_ + row) * H_ + k0 + c8]);
        }
        #pragma unroll
        for (int i = 0; i < 4; i++) {
            int e = tid + i * 256;
            int row = e >> 4, c8 = (e & 15) * 8;
            cp16(&Bs[row * 136 + c8],
                 &g_wtag[(size_t)(k0 + row) * TAGS_ + c0 + c8]);
        }
        asm volatile("cp.async.commit_group;\n" ::);
    };

    issue_tile(0);
    issue_tile(1);
    for (int kt = 0; kt < 16; kt++) {
        if (kt < 15) asm volatile("cp.async.wait_group 1;\n" ::);
        else         asm volatile("cp.async.wait_group 0;\n" ::);
        __syncthreads();
        int s = kt % 3;
        const __nv_bfloat16* As = Asm + s * A_STG;
        const __nv_bfloat16* Bs = Bsm + s * B_STG;
        #pragma unroll
        for (int ks = 0; ks < 64; ks += 16) {
            wmma::fragment<wmma::matrix_a, 16, 16, 16, __nv_bfloat16, wmma::row_major> af[4];
            wmma::fragment<wmma::matrix_b, 16, 16, 16, __nv_bfloat16, wmma::row_major> bf[4];
            #pragma unroll
            for (int i = 0; i < 4; i++)
                wmma::load_matrix_sync(af[i], &As[(wy * 64 + i * 16) * 72 + ks], 72);
            #pragma unroll
            for (int j = 0; j < 4; j++)
                wmma::load_matrix_sync(bf[j], &Bs[ks * 136 + wx * 64 + j * 16], 136);
            #pragma unroll
            for (int i = 0; i < 4; i++)
                #pragma unroll
                for (int j = 0; j < 4; j++)
                    wmma::mma_sync(acc[i][j], af[i], bf[j], acc[i][j]);
        }
        if (kt + 2 < 16) issue_tile(kt + 2);
    }
    __syncthreads();

    #pragma unroll
    for (int i = 0; i < 4; i++)
        #pragma unroll
        for (int j = 0; j < 4; j++)
            wmma::store_matrix_sync(&Osm[(wy * 64 + i * 16) * 136 + wx * 64 + j * 16],
                                    acc[i][j], 136, wmma::mem_row_major);
    __syncthreads();

    const int p = tid >> 7;
    const int c = tid & 127;
    float m = -1e30f;
    #pragma unroll 8
    for (int i = 0; i < 128; i++) m = fmaxf(m, Osm[(p * 128 + i) * 136 + c]);
    red[p * 128 + c] = m;
    __syncthreads();
    float M = fmaxf(red[c], red[128 + c]);
    float ssum = 0.f;
    #pragma unroll 8
    for (int i = 0; i < 128; i++) ssum += __expf(Osm[(p * 128 + i) * 136 + c] - M);
    __syncthreads();
    red[p * 128 + c] = ssum;
    __syncthreads();
    float lse = M + logf(red[c] + red[128 + c]);
    #pragma unroll 8
    for (int i = 0; i < 128; i++) {
        int b = p * 128 + i;
        out[((size_t)t * B_ + b) * TAGS_ + c0 + c] = Osm[b * 136 + c] - lse;
    }
}

// ---------------- launch -----------------------------------------------------
extern "C" void kernel_launch(void* const* d_in, const int* in_sizes, int n_in,
                              void* d_out, int out_size) {
    const int*   sentence = (const int*)  d_in[0];
    const float* emb      = (const float*)d_in[1];
    const float* Wg       = (const float*)d_in[2];
    const float* bg       = (const float*)d_in[3];
    const float* theta    = (const float*)d_in[4];
    const float* Wp       = (const float*)d_in[5];
    const float* bp       = (const float*)d_in[6];
    const float* W_tag    = (const float*)d_in[7];
    // d_in[8] = b_tag: cancels in log_softmax over batch axis -> unused
    float* out = (float*)d_out;

    cudaFuncSetAttribute(embproj_kernel, cudaFuncAttributeMaxDynamicSharedMemorySize, EP_SMEM);
    cudaFuncSetAttribute(lstm_kernel,    cudaFuncAttributeMaxDynamicSharedMemorySize, LSTM_SMEM);
    cudaFuncSetAttribute(tag_kernel,     cudaFuncAttributeMaxDynamicSharedMemorySize, TAG_SMEM);

    wtag_convert<<<(H_ * TAGS_) / 256, 256>>>(W_tag);
    embproj_kernel<<<V_ / 256, 256, EP_SMEM>>>(emb, Wg);
    lstm_kernel<<<B_ / 2, 512, LSTM_SMEM>>>(sentence, Wg, bg, theta, Wp, bp);
    dim3 g3(TAGS_ / 128, T_);
    tag_kernel<<<g3, 256, TAG_SMEM>>>(out);
}